// round 1
// baseline (speedup 1.0000x reference)
#include <cuda_runtime.h>
#include <math.h>
#include <stdint.h>

// ---------------- problem constants ----------------
// B=4 S=2048 D=1024 H=16 HD=64 F=4096 E=8 K=2, T=8192
#define T_ 8192
#define S_ 2048
#define D_ 1024
#define H_ 16
#define HD_ 64
#define F_ 4096
#define E_ 8
#define BH_ 64   // B*H

// ---------------- scratch (static device globals; no allocs) ----------------
__device__ float d_qt[T_ * D_];            // [bh, s, hd]
__device__ float d_kt[T_ * D_];
__device__ float d_vt[T_ * D_];
__device__ float d_scores[268435456];      // [bh, q, k]  (64*2048*2048) 1 GiB
__device__ float d_attnx[T_ * D_];         // attention out back in [t, d]
__device__ float d_tmp[T_ * D_];           // O-proj result
__device__ float d_x1[T_ * D_];            // after LN1
__device__ float d_moe[T_ * D_];           // MoE combined output
__device__ float d_h[67108864];            // expert hidden, compact rows [16384, 4096]
__device__ float d_gsc[T_ * E_];           // gate softmax scores
__device__ int   d_tok_e[T_ * 2];
__device__ float d_tok_w[T_ * 2];
__device__ int   d_list[T_ * 2];           // compact token lists per expert
__device__ float d_wl[T_ * 2];
__device__ int   d_cnt[E_];
__device__ int   d_fill[E_];
__device__ int   d_base[E_];

// ---------------- zero counters + moe accumulator ----------------
__global__ void k_zero() {
    int i = blockIdx.x * 256 + threadIdx.x;
    if (i < T_ * D_) d_moe[i] = 0.f;
    if (i < E_) { d_cnt[i] = 0; d_fill[i] = 0; }
}

// ---------------- QKV projection: x[T,D] @ W[D,D] + b, store [bh,s,hd] ----------------
__global__ __launch_bounds__(256) void k_qkv(
    const float* __restrict__ x,
    const float* __restrict__ Wq, const float* __restrict__ bq,
    const float* __restrict__ Wk, const float* __restrict__ bk,
    const float* __restrict__ Wv, const float* __restrict__ bv)
{
    const int which = blockIdx.z;
    const float* __restrict__ W    = which == 0 ? Wq : (which == 1 ? Wk : Wv);
    const float* __restrict__ bias = which == 0 ? bq : (which == 1 ? bk : bv);
    float* dst = which == 0 ? d_qt : (which == 1 ? d_kt : d_vt);

    const int tid = threadIdx.x;
    const int row0 = blockIdx.y * 128, col0 = blockIdx.x * 128;
    __shared__ float As[8][128];
    __shared__ float Bs[8][128];
    float acc[8][8];
#pragma unroll
    for (int i = 0; i < 8; i++)
#pragma unroll
        for (int j = 0; j < 8; j++) acc[i][j] = 0.f;

    const int arow = tid >> 1, ak4 = (tid & 1) * 4;
    const int bkr = tid >> 5, bn4 = (tid & 31) * 4;
    const int tx = tid & 15, ty = tid >> 4;

    for (int k0 = 0; k0 < D_; k0 += 8) {
        float4 a4 = *(const float4*)(x + (size_t)(row0 + arow) * D_ + k0 + ak4);
        As[ak4 + 0][arow] = a4.x; As[ak4 + 1][arow] = a4.y;
        As[ak4 + 2][arow] = a4.z; As[ak4 + 3][arow] = a4.w;
        *(float4*)&Bs[bkr][bn4] = *(const float4*)(W + (size_t)(k0 + bkr) * D_ + col0 + bn4);
        __syncthreads();
#pragma unroll
        for (int kk = 0; kk < 8; kk++) {
            float ra[8], rb[8];
#pragma unroll
            for (int i = 0; i < 8; i++) ra[i] = As[kk][ty * 8 + i];
#pragma unroll
            for (int j = 0; j < 8; j++) rb[j] = Bs[kk][tx * 8 + j];
#pragma unroll
            for (int i = 0; i < 8; i++)
#pragma unroll
                for (int j = 0; j < 8; j++) acc[i][j] += ra[i] * rb[j];
        }
        __syncthreads();
    }
#pragma unroll
    for (int i = 0; i < 8; i++) {
        int t = row0 + ty * 8 + i;
        int bi = t >> 11, s = t & 2047;
#pragma unroll
        for (int j = 0; j < 8; j++) {
            int c = col0 + tx * 8 + j;
            int h = c >> 6, hd = c & 63;
            dst[(((size_t)(bi * H_ + h)) * S_ + s) * HD_ + hd] = acc[i][j] + bias[c];
        }
    }
}

// ---------------- scores = q @ k^T / 8 : NT gemm, K=64 per head ----------------
__global__ __launch_bounds__(256) void k_scores() {
    const int bh = blockIdx.z;
    const float* __restrict__ A  = d_qt + (size_t)bh * S_ * HD_;
    const float* __restrict__ Bm = d_kt + (size_t)bh * S_ * HD_;
    float* Cm = d_scores + (size_t)bh * S_ * S_;

    const int tid = threadIdx.x;
    const int row0 = blockIdx.y * 128, col0 = blockIdx.x * 128;
    __shared__ float As[8][128];
    __shared__ float Bs[8][128];
    float acc[8][8];
#pragma unroll
    for (int i = 0; i < 8; i++)
#pragma unroll
        for (int j = 0; j < 8; j++) acc[i][j] = 0.f;

    const int arow = tid >> 1, ak4 = (tid & 1) * 4;
    const int tx = tid & 15, ty = tid >> 4;

    for (int k0 = 0; k0 < HD_; k0 += 8) {
        float4 a4 = *(const float4*)(A + (size_t)(row0 + arow) * HD_ + k0 + ak4);
        As[ak4 + 0][arow] = a4.x; As[ak4 + 1][arow] = a4.y;
        As[ak4 + 2][arow] = a4.z; As[ak4 + 3][arow] = a4.w;
        float4 b4 = *(const float4*)(Bm + (size_t)(col0 + arow) * HD_ + k0 + ak4);
        Bs[ak4 + 0][arow] = b4.x; Bs[ak4 + 1][arow] = b4.y;
        Bs[ak4 + 2][arow] = b4.z; Bs[ak4 + 3][arow] = b4.w;
        __syncthreads();
#pragma unroll
        for (int kk = 0; kk < 8; kk++) {
            float ra[8], rb[8];
#pragma unroll
            for (int i = 0; i < 8; i++) ra[i] = As[kk][ty * 8 + i];
#pragma unroll
            for (int j = 0; j < 8; j++) rb[j] = Bs[kk][tx * 8 + j];
#pragma unroll
            for (int i = 0; i < 8; i++)
#pragma unroll
                for (int j = 0; j < 8; j++) acc[i][j] += ra[i] * rb[j];
        }
        __syncthreads();
    }
#pragma unroll
    for (int i = 0; i < 8; i++)
#pragma unroll
        for (int j = 0; j < 8; j++)
            Cm[(size_t)(row0 + ty * 8 + i) * S_ + col0 + tx * 8 + j] = acc[i][j] * 0.125f;
}

// ---------------- row softmax over 2048 keys ----------------
__global__ __launch_bounds__(256) void k_softmax() {
    float* r = d_scores + (size_t)blockIdx.x * S_;
    __shared__ float red[256];
    const int tid = threadIdx.x;
    float m = -1e30f;
    for (int i = tid; i < S_; i += 256) m = fmaxf(m, r[i]);
    red[tid] = m; __syncthreads();
    for (int o = 128; o > 0; o >>= 1) { if (tid < o) red[tid] = fmaxf(red[tid], red[tid + o]); __syncthreads(); }
    m = red[0]; __syncthreads();
    float s = 0.f;
    for (int i = tid; i < S_; i += 256) { float e = expf(r[i] - m); r[i] = e; s += e; }
    red[tid] = s; __syncthreads();
    for (int o = 128; o > 0; o >>= 1) { if (tid < o) red[tid] += red[tid + o]; __syncthreads(); }
    float inv = 1.f / red[0];
    for (int i = tid; i < S_; i += 256) r[i] *= inv;
}

// ---------------- out = attn @ v : [2048,2048]@[2048,64] per head ----------------
__global__ __launch_bounds__(256) void k_av() {
    const int bh = blockIdx.z;
    const int row0 = blockIdx.y * 128;
    const float* __restrict__ A = d_scores + (size_t)bh * S_ * S_;
    const float* __restrict__ V = d_vt + (size_t)bh * S_ * HD_;
    __shared__ float As[8][128];
    __shared__ float Bs[8][64];
    float acc[8][4];
#pragma unroll
    for (int i = 0; i < 8; i++)
#pragma unroll
        for (int j = 0; j < 4; j++) acc[i][j] = 0.f;

    const int tid = threadIdx.x;
    const int arow = tid >> 1, ak4 = (tid & 1) * 4;
    const int bkr = tid >> 5, bn2 = (tid & 31) * 2;
    const int tx = tid & 15, ty = tid >> 4;

    for (int k0 = 0; k0 < S_; k0 += 8) {
        float4 a4 = *(const float4*)(A + (size_t)(row0 + arow) * S_ + k0 + ak4);
        As[ak4 + 0][arow] = a4.x; As[ak4 + 1][arow] = a4.y;
        As[ak4 + 2][arow] = a4.z; As[ak4 + 3][arow] = a4.w;
        float2 b2 = *(const float2*)(V + (size_t)(k0 + bkr) * HD_ + bn2);
        Bs[bkr][bn2] = b2.x; Bs[bkr][bn2 + 1] = b2.y;
        __syncthreads();
#pragma unroll
        for (int kk = 0; kk < 8; kk++) {
            float ra[8], rb[4];
#pragma unroll
            for (int i = 0; i < 8; i++) ra[i] = As[kk][ty * 8 + i];
#pragma unroll
            for (int j = 0; j < 4; j++) rb[j] = Bs[kk][tx * 4 + j];
#pragma unroll
            for (int i = 0; i < 8; i++)
#pragma unroll
                for (int j = 0; j < 4; j++) acc[i][j] += ra[i] * rb[j];
        }
        __syncthreads();
    }
    const int b = bh >> 4, h = bh & 15;
#pragma unroll
    for (int i = 0; i < 8; i++) {
        int q = row0 + ty * 8 + i;
#pragma unroll
        for (int j = 0; j < 4; j++)
            d_attnx[((size_t)(b * S_ + q)) * D_ + h * HD_ + tx * 4 + j] = acc[i][j];
    }
}

// ---------------- O projection: attnx[T,D] @ Wo + bo -> d_tmp ----------------
__global__ __launch_bounds__(256) void k_oproj(const float* __restrict__ W, const float* __restrict__ bias) {
    const int tid = threadIdx.x;
    const int row0 = blockIdx.y * 128, col0 = blockIdx.x * 128;
    __shared__ float As[8][128];
    __shared__ float Bs[8][128];
    float acc[8][8];
#pragma unroll
    for (int i = 0; i < 8; i++)
#pragma unroll
        for (int j = 0; j < 8; j++) acc[i][j] = 0.f;

    const int arow = tid >> 1, ak4 = (tid & 1) * 4;
    const int bkr = tid >> 5, bn4 = (tid & 31) * 4;
    const int tx = tid & 15, ty = tid >> 4;

    for (int k0 = 0; k0 < D_; k0 += 8) {
        float4 a4 = *(const float4*)(d_attnx + (size_t)(row0 + arow) * D_ + k0 + ak4);
        As[ak4 + 0][arow] = a4.x; As[ak4 + 1][arow] = a4.y;
        As[ak4 + 2][arow] = a4.z; As[ak4 + 3][arow] = a4.w;
        *(float4*)&Bs[bkr][bn4] = *(const float4*)(W + (size_t)(k0 + bkr) * D_ + col0 + bn4);
        __syncthreads();
#pragma unroll
        for (int kk = 0; kk < 8; kk++) {
            float ra[8], rb[8];
#pragma unroll
            for (int i = 0; i < 8; i++) ra[i] = As[kk][ty * 8 + i];
#pragma unroll
            for (int j = 0; j < 8; j++) rb[j] = Bs[kk][tx * 8 + j];
#pragma unroll
            for (int i = 0; i < 8; i++)
#pragma unroll
                for (int j = 0; j < 8; j++) acc[i][j] += ra[i] * rb[j];
        }
        __syncthreads();
    }
#pragma unroll
    for (int i = 0; i < 8; i++)
#pragma unroll
        for (int j = 0; j < 8; j++) {
            int c = col0 + tx * 8 + j;
            d_tmp[(size_t)(row0 + ty * 8 + i) * D_ + c] = acc[i][j] + bias[c];
        }
}

// ---------------- layernorm body ----------------
__device__ __forceinline__ void ln_body(const float* __restrict__ a, const float* __restrict__ add,
                                        const float* __restrict__ g, const float* __restrict__ be,
                                        float* __restrict__ out) {
    const int t = blockIdx.x, tid = threadIdx.x;
    __shared__ float v[D_];
    __shared__ float red[256];
    float s = 0.f;
    for (int j = tid; j < D_; j += 256) {
        float xv = a[(size_t)t * D_ + j] + add[(size_t)t * D_ + j];
        v[j] = xv; s += xv;
    }
    red[tid] = s; __syncthreads();
    for (int o = 128; o > 0; o >>= 1) { if (tid < o) red[tid] += red[tid + o]; __syncthreads(); }
    float mu = red[0] * (1.f / D_); __syncthreads();
    float s2 = 0.f;
    for (int j = tid; j < D_; j += 256) { float d = v[j] - mu; s2 += d * d; }
    red[tid] = s2; __syncthreads();
    for (int o = 128; o > 0; o >>= 1) { if (tid < o) red[tid] += red[tid + o]; __syncthreads(); }
    float rstd = rsqrtf(red[0] * (1.f / D_) + 1e-5f);
    for (int j = tid; j < D_; j += 256)
        out[(size_t)t * D_ + j] = (v[j] - mu) * rstd * g[j] + be[j];
}

__global__ __launch_bounds__(256) void k_ln1(const float* __restrict__ x,
                                             const float* __restrict__ g, const float* __restrict__ be) {
    ln_body(x, d_tmp, g, be, d_x1);
}
__global__ __launch_bounds__(256) void k_ln2(const float* __restrict__ g, const float* __restrict__ be,
                                             float* __restrict__ out) {
    ln_body(d_x1, d_moe, g, be, out);
}

// ---------------- gate + top-2 routing ----------------
__global__ __launch_bounds__(128) void k_route(const float* __restrict__ gW, const float* __restrict__ gb) {
    const int t = blockIdx.x, tid = threadIdx.x;
    float p[E_];
#pragma unroll
    for (int e = 0; e < E_; e++) p[e] = 0.f;
    for (int d = tid; d < D_; d += 128) {
        float xv = d_x1[(size_t)t * D_ + d];
        const float* w = gW + (size_t)d * E_;
#pragma unroll
        for (int e = 0; e < E_; e++) p[e] += xv * w[e];
    }
    __shared__ float red[128][E_];
#pragma unroll
    for (int e = 0; e < E_; e++) red[tid][e] = p[e];
    __syncthreads();
    for (int o = 64; o > 0; o >>= 1) {
        if (tid < o) {
#pragma unroll
            for (int e = 0; e < E_; e++) red[tid][e] += red[tid + o][e];
        }
        __syncthreads();
    }
    if (tid == 0) {
        float l[E_], m = -1e30f;
#pragma unroll
        for (int e = 0; e < E_; e++) { l[e] = red[0][e] + gb[e]; m = fmaxf(m, l[e]); }
        float s = 0.f;
#pragma unroll
        for (int e = 0; e < E_; e++) { l[e] = expf(l[e] - m); s += l[e]; }
        float inv = 1.f / s;
#pragma unroll
        for (int e = 0; e < E_; e++) { l[e] *= inv; d_gsc[t * E_ + e] = l[e]; }
        int i1 = 0;
#pragma unroll
        for (int e = 1; e < E_; e++) if (l[e] > l[i1]) i1 = e;   // first max on tie
        int i2 = -1;
#pragma unroll
        for (int e = 0; e < E_; e++) if (e != i1 && (i2 < 0 || l[e] > l[i2])) i2 = e;
        float tot = l[i1] + l[i2];
        d_tok_e[t * 2 + 0] = i1; d_tok_e[t * 2 + 1] = i2;
        d_tok_w[t * 2 + 0] = l[i1] / tot; d_tok_w[t * 2 + 1] = l[i2] / tot;
        atomicAdd(&d_cnt[i1], 1); atomicAdd(&d_cnt[i2], 1);
    }
}

// ---------------- aux loss + prefix sums (deterministic single block) ----------------
__global__ __launch_bounds__(256) void k_aux(float* __restrict__ aux_out) {
    __shared__ double red[256];
    __shared__ double rw[E_];
    const int tid = threadIdx.x;
    for (int e = 0; e < E_; e++) {
        double s = 0.0;
        for (int t = tid; t < T_; t += 256) s += (double)d_gsc[t * E_ + e];
        red[tid] = s; __syncthreads();
        for (int o = 128; o > 0; o >>= 1) { if (tid < o) red[tid] += red[tid + o]; __syncthreads(); }
        if (tid == 0) rw[e] = red[0] / (double)T_;
        __syncthreads();
    }
    if (tid == 0) {
        double aux = 0.0; int b = 0;
        for (int e = 0; e < E_; e++) {
            aux += ((double)d_cnt[e] / (double)(T_ * 2)) * rw[e];
            d_base[e] = b; b += d_cnt[e];
        }
        *aux_out = (float)((double)E_ * aux);
    }
}

// ---------------- build compact per-expert token lists ----------------
__global__ void k_fill() {
    const int t = blockIdx.x * 256 + threadIdx.x;
    if (t >= T_) return;
    for (int k = 0; k < 2; k++) {
        int e = d_tok_e[t * 2 + k];
        int slot = atomicAdd(&d_fill[e], 1);
        d_list[d_base[e] + slot] = t;
        d_wl[d_base[e] + slot] = d_tok_w[t * 2 + k];
    }
}

// ---------------- expert GEMM1: gather x1 rows, @ eW1[e] + eb1, gelu -> d_h ----------------
__global__ __launch_bounds__(256) void k_moe1(const float* __restrict__ eW1, const float* __restrict__ eb1) {
    const int e = blockIdx.z;
    const int cnt = d_cnt[e], base = d_base[e];
    const int row0 = blockIdx.y * 128;
    if (row0 >= cnt) return;
    const int col0 = blockIdx.x * 128;
    const float* __restrict__ W = eW1 + (size_t)e * D_ * F_;

    const int tid = threadIdx.x;
    __shared__ float As[8][128];
    __shared__ float Bs[8][128];
    float acc[8][8];
#pragma unroll
    for (int i = 0; i < 8; i++)
#pragma unroll
        for (int j = 0; j < 8; j++) acc[i][j] = 0.f;

    const int arow = tid >> 1, ak4 = (tid & 1) * 4;
    const int bkr = tid >> 5, bn4 = (tid & 31) * 4;
    const int tx = tid & 15, ty = tid >> 4;

    const int r = row0 + arow;
    const int token = d_list[base + (r < cnt ? r : 0)];
    const float* __restrict__ Arow = d_x1 + (size_t)token * D_;

    for (int k0 = 0; k0 < D_; k0 += 8) {
        float4 a4 = *(const float4*)(Arow + k0 + ak4);
        As[ak4 + 0][arow] = a4.x; As[ak4 + 1][arow] = a4.y;
        As[ak4 + 2][arow] = a4.z; As[ak4 + 3][arow] = a4.w;
        *(float4*)&Bs[bkr][bn4] = *(const float4*)(W + (size_t)(k0 + bkr) * F_ + col0 + bn4);
        __syncthreads();
#pragma unroll
        for (int kk = 0; kk < 8; kk++) {
            float ra[8], rb[8];
#pragma unroll
            for (int i = 0; i < 8; i++) ra[i] = As[kk][ty * 8 + i];
#pragma unroll
            for (int j = 0; j < 8; j++) rb[j] = Bs[kk][tx * 8 + j];
#pragma unroll
            for (int i = 0; i < 8; i++)
#pragma unroll
                for (int j = 0; j < 8; j++) acc[i][j] += ra[i] * rb[j];
        }
        __syncthreads();
    }
#pragma unroll
    for (int i = 0; i < 8; i++) {
        int rr = row0 + ty * 8 + i;
        if (rr < cnt) {
#pragma unroll
            for (int j = 0; j < 8; j++) {
                int c = col0 + tx * 8 + j;
                float v = acc[i][j] + eb1[e * F_ + c];
                d_h[(size_t)(base + rr) * F_ + c] = 0.5f * v * (1.f + erff(v * 0.70710678118654752f));
            }
        }
    }
}

// ---------------- expert GEMM2: h @ eW2[e] + eb2, weighted scatter-add into d_moe ----------------
__global__ __launch_bounds__(256) void k_moe2(const float* __restrict__ eW2, const float* __restrict__ eb2) {
    const int e = blockIdx.z;
    const int cnt = d_cnt[e], base = d_base[e];
    const int row0 = blockIdx.y * 128;
    if (row0 >= cnt) return;
    const int col0 = blockIdx.x * 128;
    const float* __restrict__ W = eW2 + (size_t)e * F_ * D_;

    const int tid = threadIdx.x;
    __shared__ float As[8][128];
    __shared__ float Bs[8][128];
    float acc[8][8];
#pragma unroll
    for (int i = 0; i < 8; i++)
#pragma unroll
        for (int j = 0; j < 8; j++) acc[i][j] = 0.f;

    const int arow = tid >> 1, ak4 = (tid & 1) * 4;
    const int bkr = tid >> 5, bn4 = (tid & 31) * 4;
    const int tx = tid & 15, ty = tid >> 4;

    const int r = row0 + arow;
    const int ar = base + (r < cnt ? r : 0);
    const float* __restrict__ Arow = d_h + (size_t)ar * F_;

    for (int k0 = 0; k0 < F_; k0 += 8) {
        float4 a4 = *(const float4*)(Arow + k0 + ak4);
        As[ak4 + 0][arow] = a4.x; As[ak4 + 1][arow] = a4.y;
        As[ak4 + 2][arow] = a4.z; As[ak4 + 3][arow] = a4.w;
        *(float4*)&Bs[bkr][bn4] = *(const float4*)(W + (size_t)(k0 + bkr) * D_ + col0 + bn4);
        __syncthreads();
#pragma unroll
        for (int kk = 0; kk < 8; kk++) {
            float ra[8], rb[8];
#pragma unroll
            for (int i = 0; i < 8; i++) ra[i] = As[kk][ty * 8 + i];
#pragma unroll
            for (int j = 0; j < 8; j++) rb[j] = Bs[kk][tx * 8 + j];
#pragma unroll
            for (int i = 0; i < 8; i++)
#pragma unroll
                for (int j = 0; j < 8; j++) acc[i][j] += ra[i] * rb[j];
        }
        __syncthreads();
    }
#pragma unroll
    for (int i = 0; i < 8; i++) {
        int rr = row0 + ty * 8 + i;
        if (rr < cnt) {
            int token = d_list[base + rr];
            float w = d_wl[base + rr];
#pragma unroll
            for (int j = 0; j < 8; j++) {
                int c = col0 + tx * 8 + j;
                atomicAdd(&d_moe[(size_t)token * D_ + c], w * (acc[i][j] + eb2[e * D_ + c]));
            }
        }
    }
}

// ---------------- launch ----------------
extern "C" void kernel_launch(void* const* d_in, const int* in_sizes, int n_in,
                              void* d_out, int out_size) {
    const float* x     = (const float*)d_in[0];
    const float* Wq    = (const float*)d_in[1];
    const float* bq    = (const float*)d_in[2];
    const float* Wk    = (const float*)d_in[3];
    const float* bk    = (const float*)d_in[4];
    const float* Wv    = (const float*)d_in[5];
    const float* bv    = (const float*)d_in[6];
    const float* Wo    = (const float*)d_in[7];
    const float* bo    = (const float*)d_in[8];
    const float* g1    = (const float*)d_in[9];
    const float* beta1 = (const float*)d_in[10];
    const float* gateW = (const float*)d_in[11];
    const float* gateb = (const float*)d_in[12];
    const float* eW1   = (const float*)d_in[13];
    const float* eb1   = (const float*)d_in[14];
    const float* eW2   = (const float*)d_in[15];
    const float* eb2   = (const float*)d_in[16];
    const float* g2    = (const float*)d_in[17];
    const float* beta2 = (const float*)d_in[18];
    float* out = (float*)d_out;

    k_zero<<<(T_ * D_) / 256, 256>>>();
    k_qkv<<<dim3(D_ / 128, T_ / 128, 3), 256>>>(x, Wq, bq, Wk, bk, Wv, bv);
    k_scores<<<dim3(S_ / 128, S_ / 128, BH_), 256>>>();
    k_softmax<<<BH_ * S_, 256>>>();
    k_av<<<dim3(1, S_ / 128, BH_), 256>>>();
    k_oproj<<<dim3(D_ / 128, T_ / 128), 256>>>(Wo, bo);
    k_ln1<<<T_, 256>>>(x, g1, beta1);
    k_route<<<T_, 128>>>(gateW, gateb);
    k_aux<<<1, 256>>>(out + (out_size - 1));
    k_fill<<<T_ / 256, 256>>>();
    k_moe1<<<dim3(F_ / 128, T_ / 128, E_), 256>>>(eW1, eb1);
    k_moe2<<<dim3(D_ / 128, T_ / 128, E_), 256>>>(eW2, eb2);
    k_ln2<<<T_, 256>>>(g2, beta2, out);
}

// round 5
// speedup vs baseline: 2.6007x; 2.6007x over previous
#include <cuda_runtime.h>
#include <math.h>
#include <stdint.h>

// B=4 S=2048 D=1024 H=16 HD=64 F=4096 E=8 K=2, T=8192
#define T_ 8192
#define S_ 2048
#define D_ 1024
#define H_ 16
#define HD_ 64
#define F_ 4096
#define E_ 8
#define BH_ 64

// ---------------- scratch ----------------
__device__ float d_qt[T_ * D_];
__device__ float d_kt[T_ * D_];
__device__ float d_vt[T_ * D_];
__device__ float d_scores[268435456];   // [bh,q,k] 1 GiB
__device__ float d_attnx[T_ * D_];
__device__ float d_tmp[T_ * D_];
__device__ float d_x1[T_ * D_];
__device__ float d_moe[T_ * D_];
__device__ float d_h[67108864];         // [16384, 4096]
__device__ float d_gsc[T_ * E_];
__device__ int   d_tok_e[T_ * 2];
__device__ float d_tok_w[T_ * 2];
__device__ int   d_list[T_ * 2];
__device__ float d_wl[T_ * 2];
__device__ int   d_cnt[E_];
__device__ int   d_fill[E_];
__device__ int   d_base[E_];

// ---------------- tf32 mma helpers ----------------
__device__ __forceinline__ unsigned f2tf(float f) {
    unsigned u; asm("cvt.rna.tf32.f32 %0, %1;" : "=r"(u) : "f"(f)); return u;
}
__device__ __forceinline__ void mma8(float* c, const unsigned* a, const unsigned* b) {
    asm volatile("mma.sync.aligned.m16n8k8.row.col.f32.tf32.tf32.f32 "
                 "{%0,%1,%2,%3},{%4,%5,%6,%7},{%8,%9},{%0,%1,%2,%3};"
                 : "+f"(c[0]), "+f"(c[1]), "+f"(c[2]), "+f"(c[3])
                 : "r"(a[0]), "r"(a[1]), "r"(a[2]), "r"(a[3]), "r"(b[0]), "r"(b[1]));
}

// compute one k16 slab from smem tiles; warp tile = MT*16 rows x NT2*8 cols
template <int MT, int NT2, int LDB>
__device__ __forceinline__ void compute_k16(const unsigned As[16][136], const unsigned Bs[16][LDB],
                                            int rm, int cn, int lane, float c[MT][NT2][4]) {
    const int tg = lane & 3, g = lane >> 2;
#pragma unroll
    for (int ks = 0; ks < 16; ks += 8) {
        unsigned a[MT][4], b[NT2][2];
#pragma unroll
        for (int i = 0; i < MT; i++) {
            a[i][0] = As[ks + tg][rm + i * 16 + g];
            a[i][1] = As[ks + tg][rm + i * 16 + g + 8];
            a[i][2] = As[ks + tg + 4][rm + i * 16 + g];
            a[i][3] = As[ks + tg + 4][rm + i * 16 + g + 8];
        }
#pragma unroll
        for (int j = 0; j < NT2; j++) {
            b[j][0] = Bs[ks + tg][cn + j * 8 + g];
            b[j][1] = Bs[ks + tg + 4][cn + j * 8 + g];
        }
#pragma unroll
        for (int i = 0; i < MT; i++)
#pragma unroll
            for (int j = 0; j < NT2; j++) mma8(c[i][j], a[i], b[j]);
    }
}

// ---------------- zero ----------------
__global__ void k_zero() {
    int i = blockIdx.x * 256 + threadIdx.x;
    if (i < T_ * D_) d_moe[i] = 0.f;
    if (i < E_) { d_cnt[i] = 0; d_fill[i] = 0; }
}

// ============ generic NN 128x128 tf32 gemm body (A row-gatherable) ============
// ARowF: (int r)->const float* row base ptr; EpiF: (int r,int c,float v)
template <class ARowF, class EpiF>
__device__ __forceinline__ void gemm128_nn(ARowF arow_f, const float* __restrict__ B, int ldb,
                                           int col0, int nk, EpiF epi) {
    __shared__ unsigned As[16][136];
    __shared__ unsigned Bs[16][136];
    const int tid = threadIdx.x, lane = tid & 31, warp = tid >> 5;
    const int rm = (warp & 1) * 64, cn = (warp >> 1) * 32;
    float c[4][4][4];
#pragma unroll
    for (int i = 0; i < 4; i++)
#pragma unroll
        for (int j = 0; j < 4; j++)
#pragma unroll
            for (int q = 0; q < 4; q++) c[i][j][q] = 0.f;

    const int ar = tid >> 1, ak = (tid & 1) * 8;
    const int bkr = tid >> 4, bn = (tid & 15) * 8;
    const float* Ap = arow_f(ar);

    float4 ra0, ra1, rb0, rb1;
    ra0 = *(const float4*)(Ap + ak);
    ra1 = *(const float4*)(Ap + ak + 4);
    rb0 = *(const float4*)(B + (size_t)bkr * ldb + col0 + bn);
    rb1 = *(const float4*)(B + (size_t)bkr * ldb + col0 + bn + 4);

    for (int kt = 0; kt < nk; kt++) {
        As[ak + 0][ar] = f2tf(ra0.x); As[ak + 1][ar] = f2tf(ra0.y);
        As[ak + 2][ar] = f2tf(ra0.z); As[ak + 3][ar] = f2tf(ra0.w);
        As[ak + 4][ar] = f2tf(ra1.x); As[ak + 5][ar] = f2tf(ra1.y);
        As[ak + 6][ar] = f2tf(ra1.z); As[ak + 7][ar] = f2tf(ra1.w);
        Bs[bkr][bn + 0] = f2tf(rb0.x); Bs[bkr][bn + 1] = f2tf(rb0.y);
        Bs[bkr][bn + 2] = f2tf(rb0.z); Bs[bkr][bn + 3] = f2tf(rb0.w);
        Bs[bkr][bn + 4] = f2tf(rb1.x); Bs[bkr][bn + 5] = f2tf(rb1.y);
        Bs[bkr][bn + 6] = f2tf(rb1.z); Bs[bkr][bn + 7] = f2tf(rb1.w);
        __syncthreads();
        if (kt + 1 < nk) {
            int k0 = (kt + 1) * 16;
            ra0 = *(const float4*)(Ap + k0 + ak);
            ra1 = *(const float4*)(Ap + k0 + ak + 4);
            rb0 = *(const float4*)(B + (size_t)(k0 + bkr) * ldb + col0 + bn);
            rb1 = *(const float4*)(B + (size_t)(k0 + bkr) * ldb + col0 + bn + 4);
        }
        compute_k16<4, 4, 136>(As, Bs, rm, cn, lane, c);
        __syncthreads();
    }
    const int tg = lane & 3, g = lane >> 2;
#pragma unroll
    for (int i = 0; i < 4; i++) {
        int r0 = rm + i * 16 + g;
#pragma unroll
        for (int j = 0; j < 4; j++) {
            int c0 = cn + j * 8 + tg * 2;
            epi(r0, c0, c[i][j][0]); epi(r0, c0 + 1, c[i][j][1]);
            epi(r0 + 8, c0, c[i][j][2]); epi(r0 + 8, c0 + 1, c[i][j][3]);
        }
    }
}

// ---------------- QKV projection ----------------
__global__ __launch_bounds__(256) void k_qkv(
    const float* __restrict__ x,
    const float* __restrict__ Wq, const float* __restrict__ bq,
    const float* __restrict__ Wk, const float* __restrict__ bk,
    const float* __restrict__ Wv, const float* __restrict__ bv)
{
    const int which = blockIdx.z;
    const float* __restrict__ W    = which == 0 ? Wq : (which == 1 ? Wk : Wv);
    const float* __restrict__ bias = which == 0 ? bq : (which == 1 ? bk : bv);
    float* dst = which == 0 ? d_qt : (which == 1 ? d_kt : d_vt);
    const int row0 = blockIdx.y * 128, col0 = blockIdx.x * 128;
    gemm128_nn([&](int r) { return x + (size_t)(row0 + r) * D_; }, W, D_, col0, D_ / 16,
        [&](int r, int cc, float v) {
            int t = row0 + r, cg = col0 + cc;
            int bi = t >> 11, s = t & 2047, h = cg >> 6, hd = cg & 63;
            dst[(((size_t)(bi * H_ + h)) * S_ + s) * HD_ + hd] = v + bias[cg];
        });
}

// ---------------- O projection ----------------
__global__ __launch_bounds__(256) void k_oproj(const float* __restrict__ W, const float* __restrict__ bias) {
    const int row0 = blockIdx.y * 128, col0 = blockIdx.x * 128;
    gemm128_nn([&](int r) { return d_attnx + (size_t)(row0 + r) * D_; }, W, D_, col0, D_ / 16,
        [&](int r, int cc, float v) {
            d_tmp[(size_t)(row0 + r) * D_ + col0 + cc] = v + bias[col0 + cc];
        });
}

// ---------------- MoE GEMM1 (gather + gelu) ----------------
__global__ __launch_bounds__(256) void k_moe1(const float* __restrict__ eW1, const float* __restrict__ eb1) {
    const int e = blockIdx.z;
    const int cnt = d_cnt[e], base = d_base[e];
    const int row0 = blockIdx.y * 128;
    if (row0 >= cnt) return;
    const int col0 = blockIdx.x * 128;
    const float* __restrict__ W = eW1 + (size_t)e * D_ * F_;
    gemm128_nn([&](int r) {
            int rr = row0 + r;
            int token = d_list[base + (rr < cnt ? rr : 0)];
            return d_x1 + (size_t)token * D_;
        }, W, F_, col0, D_ / 16,
        [&](int r, int cc, float v) {
            int rr = row0 + r;
            if (rr < cnt) {
                float t = v + eb1[e * F_ + col0 + cc];
                d_h[(size_t)(base + rr) * F_ + col0 + cc] =
                    0.5f * t * (1.f + erff(t * 0.70710678118654752f));
            }
        });
}

// ---------------- MoE GEMM2 (weighted scatter-add) ----------------
__global__ __launch_bounds__(256) void k_moe2(const float* __restrict__ eW2, const float* __restrict__ eb2) {
    const int e = blockIdx.z;
    const int cnt = d_cnt[e], base = d_base[e];
    const int row0 = blockIdx.y * 128;
    if (row0 >= cnt) return;
    const int col0 = blockIdx.x * 128;
    const float* __restrict__ W = eW2 + (size_t)e * F_ * D_;
    gemm128_nn([&](int r) {
            int rr = row0 + r;
            return d_h + (size_t)(base + (rr < cnt ? rr : 0)) * F_;
        }, W, D_, col0, F_ / 16,
        [&](int r, int cc, float v) {
            int rr = row0 + r;
            if (rr < cnt) {
                int token = d_list[base + rr];
                float w = d_wl[base + rr];
                atomicAdd(&d_moe[(size_t)token * D_ + col0 + cc],
                          w * (v + eb2[e * D_ + col0 + cc]));
            }
        });
}

// ---------------- scores = q@k^T/8 (NT, per-head K=64) ----------------
__global__ __launch_bounds__(256) void k_scores() {
    const int bh = blockIdx.z;
    const float* __restrict__ A  = d_qt + (size_t)bh * S_ * HD_;
    const float* __restrict__ Kt = d_kt + (size_t)bh * S_ * HD_;
    float* Cm = d_scores + (size_t)bh * S_ * S_;
    const int row0 = blockIdx.y * 128, col0 = blockIdx.x * 128;

    __shared__ unsigned As[16][136];
    __shared__ unsigned Bs[16][136];
    const int tid = threadIdx.x, lane = tid & 31, warp = tid >> 5;
    const int rm = (warp & 1) * 64, cn = (warp >> 1) * 32;
    float c[4][4][4];
#pragma unroll
    for (int i = 0; i < 4; i++)
#pragma unroll
        for (int j = 0; j < 4; j++)
#pragma unroll
            for (int q = 0; q < 4; q++) c[i][j][q] = 0.f;

    const int ar = tid >> 1, ak = (tid & 1) * 8;
    const float* Ap = A + (size_t)(row0 + ar) * HD_;
    const float* Bp = Kt + (size_t)(col0 + ar) * HD_;

    float4 ra0, ra1, rb0, rb1;
    ra0 = *(const float4*)(Ap + ak);     ra1 = *(const float4*)(Ap + ak + 4);
    rb0 = *(const float4*)(Bp + ak);     rb1 = *(const float4*)(Bp + ak + 4);

    for (int kt = 0; kt < HD_ / 16; kt++) {
        As[ak + 0][ar] = f2tf(ra0.x); As[ak + 1][ar] = f2tf(ra0.y);
        As[ak + 2][ar] = f2tf(ra0.z); As[ak + 3][ar] = f2tf(ra0.w);
        As[ak + 4][ar] = f2tf(ra1.x); As[ak + 5][ar] = f2tf(ra1.y);
        As[ak + 6][ar] = f2tf(ra1.z); As[ak + 7][ar] = f2tf(ra1.w);
        Bs[ak + 0][ar] = f2tf(rb0.x); Bs[ak + 1][ar] = f2tf(rb0.y);
        Bs[ak + 2][ar] = f2tf(rb0.z); Bs[ak + 3][ar] = f2tf(rb0.w);
        Bs[ak + 4][ar] = f2tf(rb1.x); Bs[ak + 5][ar] = f2tf(rb1.y);
        Bs[ak + 6][ar] = f2tf(rb1.z); Bs[ak + 7][ar] = f2tf(rb1.w);
        __syncthreads();
        if (kt + 1 < HD_ / 16) {
            int k0 = (kt + 1) * 16;
            ra0 = *(const float4*)(Ap + k0 + ak); ra1 = *(const float4*)(Ap + k0 + ak + 4);
            rb0 = *(const float4*)(Bp + k0 + ak); rb1 = *(const float4*)(Bp + k0 + ak + 4);
        }
        compute_k16<4, 4, 136>(As, Bs, rm, cn, lane, c);
        __syncthreads();
    }
    const int tg = lane & 3, g = lane >> 2;
#pragma unroll
    for (int i = 0; i < 4; i++) {
        int r0 = row0 + rm + i * 16 + g;
#pragma unroll
        for (int j = 0; j < 4; j++) {
            int c0 = col0 + cn + j * 8 + tg * 2;
            Cm[(size_t)r0 * S_ + c0]           = c[i][j][0] * 0.125f;
            Cm[(size_t)r0 * S_ + c0 + 1]       = c[i][j][1] * 0.125f;
            Cm[(size_t)(r0 + 8) * S_ + c0]     = c[i][j][2] * 0.125f;
            Cm[(size_t)(r0 + 8) * S_ + c0 + 1] = c[i][j][3] * 0.125f;
        }
    }
}

// ---------------- softmax (1 read + 1 write) ----------------
__global__ __launch_bounds__(256) void k_softmax() {
    float4* r = (float4*)(d_scores + (size_t)blockIdx.x * S_);
    const int tid = threadIdx.x, lane = tid & 31, warp = tid >> 5;
    __shared__ float sm[8];
    float4 v0 = r[tid], v1 = r[tid + 256];
    float m = fmaxf(fmaxf(fmaxf(v0.x, v0.y), fmaxf(v0.z, v0.w)),
                    fmaxf(fmaxf(v1.x, v1.y), fmaxf(v1.z, v1.w)));
#pragma unroll
    for (int o = 16; o > 0; o >>= 1) m = fmaxf(m, __shfl_xor_sync(~0u, m, o));
    if (lane == 0) sm[warp] = m;
    __syncthreads();
    m = sm[0];
#pragma unroll
    for (int w = 1; w < 8; w++) m = fmaxf(m, sm[w]);
    __syncthreads();
    v0.x = __expf(v0.x - m); v0.y = __expf(v0.y - m); v0.z = __expf(v0.z - m); v0.w = __expf(v0.w - m);
    v1.x = __expf(v1.x - m); v1.y = __expf(v1.y - m); v1.z = __expf(v1.z - m); v1.w = __expf(v1.w - m);
    float s = v0.x + v0.y + v0.z + v0.w + v1.x + v1.y + v1.z + v1.w;
#pragma unroll
    for (int o = 16; o > 0; o >>= 1) s += __shfl_xor_sync(~0u, s, o);
    if (lane == 0) sm[warp] = s;
    __syncthreads();
    s = sm[0] + sm[1] + sm[2] + sm[3] + sm[4] + sm[5] + sm[6] + sm[7];
    float inv = 1.f / s;
    v0.x *= inv; v0.y *= inv; v0.z *= inv; v0.w *= inv;
    v1.x *= inv; v1.y *= inv; v1.z *= inv; v1.w *= inv;
    r[tid] = v0; r[tid + 256] = v1;
}

// ---------------- attn@V (128x64 tile, nk=128) ----------------
__global__ __launch_bounds__(256) void k_av() {
    const int bh = blockIdx.z;
    const int row0 = blockIdx.y * 128;
    const float* __restrict__ A = d_scores + (size_t)bh * S_ * S_;
    const float* __restrict__ V = d_vt + (size_t)bh * S_ * HD_;

    __shared__ unsigned As[16][136];
    __shared__ unsigned Bs[16][72];
    const int tid = threadIdx.x, lane = tid & 31, warp = tid >> 5;
    const int rm = (warp & 3) * 32, cn = (warp >> 2) * 32;
    float c[2][4][4];
#pragma unroll
    for (int i = 0; i < 2; i++)
#pragma unroll
        for (int j = 0; j < 4; j++)
#pragma unroll
            for (int q = 0; q < 4; q++) c[i][j][q] = 0.f;

    const int ar = tid >> 1, ak = (tid & 1) * 8;
    const int bkr = tid >> 4, bn4 = (tid & 15) * 4;
    const float* Ap = A + (size_t)(row0 + ar) * S_;

    float4 ra0, ra1, rb0;
    ra0 = *(const float4*)(Ap + ak);
    ra1 = *(const float4*)(Ap + ak + 4);
    rb0 = *(const float4*)(V + (size_t)bkr * HD_ + bn4);

    for (int kt = 0; kt < S_ / 16; kt++) {
        As[ak + 0][ar] = f2tf(ra0.x); As[ak + 1][ar] = f2tf(ra0.y);
        As[ak + 2][ar] = f2tf(ra0.z); As[ak + 3][ar] = f2tf(ra0.w);
        As[ak + 4][ar] = f2tf(ra1.x); As[ak + 5][ar] = f2tf(ra1.y);
        As[ak + 6][ar] = f2tf(ra1.z); As[ak + 7][ar] = f2tf(ra1.w);
        Bs[bkr][bn4 + 0] = f2tf(rb0.x); Bs[bkr][bn4 + 1] = f2tf(rb0.y);
        Bs[bkr][bn4 + 2] = f2tf(rb0.z); Bs[bkr][bn4 + 3] = f2tf(rb0.w);
        __syncthreads();
        if (kt + 1 < S_ / 16) {
            int k0 = (kt + 1) * 16;
            ra0 = *(const float4*)(Ap + k0 + ak);
            ra1 = *(const float4*)(Ap + k0 + ak + 4);
            rb0 = *(const float4*)(V + (size_t)(k0 + bkr) * HD_ + bn4);
        }
        compute_k16<2, 4, 72>(As, Bs, rm, cn, lane, c);
        __syncthreads();
    }
    const int b = bh >> 4, h = bh & 15;
    const int tg = lane & 3, g = lane >> 2;
#pragma unroll
    for (int i = 0; i < 2; i++) {
        int r0 = row0 + rm + i * 16 + g;
#pragma unroll
        for (int j = 0; j < 4; j++) {
            int c0 = cn + j * 8 + tg * 2;
            d_attnx[((size_t)(b * S_ + r0)) * D_ + h * HD_ + c0]           = c[i][j][0];
            d_attnx[((size_t)(b * S_ + r0)) * D_ + h * HD_ + c0 + 1]       = c[i][j][1];
            d_attnx[((size_t)(b * S_ + r0 + 8)) * D_ + h * HD_ + c0]       = c[i][j][2];
            d_attnx[((size_t)(b * S_ + r0 + 8)) * D_ + h * HD_ + c0 + 1]   = c[i][j][3];
        }
    }
}

// ---------------- layernorm ----------------
__device__ __forceinline__ void ln_body(const float* __restrict__ a, const float* __restrict__ add,
                                        const float* __restrict__ g, const float* __restrict__ be,
                                        float* __restrict__ out) {
    const int t = blockIdx.x, tid = threadIdx.x;
    __shared__ float v[D_];
    __shared__ float red[256];
    float s = 0.f;
    for (int j = tid; j < D_; j += 256) {
        float xv = a[(size_t)t * D_ + j] + add[(size_t)t * D_ + j];
        v[j] = xv; s += xv;
    }
    red[tid] = s; __syncthreads();
    for (int o = 128; o > 0; o >>= 1) { if (tid < o) red[tid] += red[tid + o]; __syncthreads(); }
    float mu = red[0] * (1.f / D_); __syncthreads();
    float s2 = 0.f;
    for (int j = tid; j < D_; j += 256) { float d = v[j] - mu; s2 += d * d; }
    red[tid] = s2; __syncthreads();
    for (int o = 128; o > 0; o >>= 1) { if (tid < o) red[tid] += red[tid + o]; __syncthreads(); }
    float rstd = rsqrtf(red[0] * (1.f / D_) + 1e-5f);
    for (int j = tid; j < D_; j += 256)
        out[(size_t)t * D_ + j] = (v[j] - mu) * rstd * g[j] + be[j];
}
__global__ __launch_bounds__(256) void k_ln1(const float* __restrict__ x,
                                             const float* __restrict__ g, const float* __restrict__ be) {
    ln_body(x, d_tmp, g, be, d_x1);
}
__global__ __launch_bounds__(256) void k_ln2(const float* __restrict__ g, const float* __restrict__ be,
                                             float* __restrict__ out) {
    ln_body(d_x1, d_moe, g, be, out);
}

// ---------------- routing ----------------
__global__ __launch_bounds__(128) void k_route(const float* __restrict__ gW, const float* __restrict__ gb) {
    const int t = blockIdx.x, tid = threadIdx.x;
    float p[E_];
#pragma unroll
    for (int e = 0; e < E_; e++) p[e] = 0.f;
    for (int d = tid; d < D_; d += 128) {
        float xv = d_x1[(size_t)t * D_ + d];
        const float* w = gW + (size_t)d * E_;
#pragma unroll
        for (int e = 0; e < E_; e++) p[e] += xv * w[e];
    }
    __shared__ float red[128][E_];
#pragma unroll
    for (int e = 0; e < E_; e++) red[tid][e] = p[e];
    __syncthreads();
    for (int o = 64; o > 0; o >>= 1) {
        if (tid < o) {
#pragma unroll
            for (int e = 0; e < E_; e++) red[tid][e] += red[tid + o][e];
        }
        __syncthreads();
    }
    if (tid == 0) {
        float l[E_], m = -1e30f;
#pragma unroll
        for (int e = 0; e < E_; e++) { l[e] = red[0][e] + gb[e]; m = fmaxf(m, l[e]); }
        float s = 0.f;
#pragma unroll
        for (int e = 0; e < E_; e++) { l[e] = expf(l[e] - m); s += l[e]; }
        float inv = 1.f / s;
#pragma unroll
        for (int e = 0; e < E_; e++) { l[e] *= inv; d_gsc[t * E_ + e] = l[e]; }
        int i1 = 0;
#pragma unroll
        for (int e = 1; e < E_; e++) if (l[e] > l[i1]) i1 = e;
        int i2 = -1;
#pragma unroll
        for (int e = 0; e < E_; e++) if (e != i1 && (i2 < 0 || l[e] > l[i2])) i2 = e;
        float tot = l[i1] + l[i2];
        d_tok_e[t * 2 + 0] = i1; d_tok_e[t * 2 + 1] = i2;
        d_tok_w[t * 2 + 0] = l[i1] / tot; d_tok_w[t * 2 + 1] = l[i2] / tot;
        atomicAdd(&d_cnt[i1], 1); atomicAdd(&d_cnt[i2], 1);
    }
}

__global__ __launch_bounds__(256) void k_aux(float* __restrict__ aux_out) {
    __shared__ double red[256];
    __shared__ double rw[E_];
    const int tid = threadIdx.x;
    for (int e = 0; e < E_; e++) {
        double s = 0.0;
        for (int t = tid; t < T_; t += 256) s += (double)d_gsc[t * E_ + e];
        red[tid] = s; __syncthreads();
        for (int o = 128; o > 0; o >>= 1) { if (tid < o) red[tid] += red[tid + o]; __syncthreads(); }
        if (tid == 0) rw[e] = red[0] / (double)T_;
        __syncthreads();
    }
    if (tid == 0) {
        double aux = 0.0; int b = 0;
        for (int e = 0; e < E_; e++) {
            aux += ((double)d_cnt[e] / (double)(T_ * 2)) * rw[e];
            d_base[e] = b; b += d_cnt[e];
        }
        *aux_out = (float)((double)E_ * aux);
    }
}

__global__ void k_fill() {
    const int t = blockIdx.x * 256 + threadIdx.x;
    if (t >= T_) return;
    for (int k = 0; k < 2; k++) {
        int e = d_tok_e[t * 2 + k];
        int slot = atomicAdd(&d_fill[e], 1);
        d_list[d_base[e] + slot] = t;
        d_wl[d_base[e] + slot] = d_tok_w[t * 2 + k];
    }
}

// ---------------- launch ----------------
extern "C" void kernel_launch(void* const* d_in, const int* in_sizes, int n_in,
                              void* d_out, int out_size) {
    const float* x     = (const float*)d_in[0];
    const float* Wq    = (const float*)d_in[1];
    const float* bq    = (const float*)d_in[2];
    const float* Wk    = (const float*)d_in[3];
    const float* bk    = (const float*)d_in[4];
    const float* Wv    = (const float*)d_in[5];
    const float* bv    = (const float*)d_in[6];
    const float* Wo    = (const float*)d_in[7];
    const float* bo    = (const float*)d_in[8];
    const float* g1    = (const float*)d_in[9];
    const float* beta1 = (const float*)d_in[10];
    const float* gateW = (const float*)d_in[11];
    const float* gateb = (const float*)d_in[12];
    const float* eW1   = (const float*)d_in[13];
    const float* eb1   = (const float*)d_in[14];
    const float* eW2   = (const float*)d_in[15];
    const float* eb2   = (const float*)d_in[16];
    const float* g2    = (const float*)d_in[17];
    const float* beta2 = (const float*)d_in[18];
    float* out = (float*)d_out;

    k_zero<<<(T_ * D_) / 256, 256>>>();
    k_qkv<<<dim3(D_ / 128, T_ / 128, 3), 256>>>(x, Wq, bq, Wk, bk, Wv, bv);
    k_scores<<<dim3(S_ / 128, S_ / 128, BH_), 256>>>();
    k_softmax<<<BH_ * S_, 256>>>();
    k_av<<<dim3(1, S_ / 128, BH_), 256>>>();
    k_oproj<<<dim3(D_ / 128, T_ / 128), 256>>>(Wo, bo);
    k_ln1<<<T_, 256>>>(x, g1, beta1);
    k_route<<<T_, 128>>>(gateW, gateb);
    k_aux<<<1, 256>>>(out + (out_size - 1));
    k_fill<<<T_ / 256, 256>>>();
    k_moe1<<<dim3(F_ / 128, T_ / 128, E_), 256>>>(eW1, eb1);
    k_moe2<<<dim3(D_ / 128, T_ / 128, E_), 256>>>(eW2, eb2);
    k_ln2<<<T_, 256>>>(g2, beta2, out);
}

// round 7
// speedup vs baseline: 2.9250x; 1.1247x over previous
#include <cuda_runtime.h>
#include <math.h>
#include <stdint.h>

// B=4 S=2048 D=1024 H=16 HD=64 F=4096 E=8 K=2, T=8192
#define T_ 8192
#define S_ 2048
#define D_ 1024
#define H_ 16
#define HD_ 64
#define F_ 4096
#define E_ 8
#define BH_ 64

// ---------------- scratch ----------------
__device__ float d_qt[T_ * D_];
__device__ float d_kt[T_ * D_];
__device__ float d_vt[T_ * D_];
__device__ float d_attnx[T_ * D_];
__device__ float d_tmp[T_ * D_];
__device__ float d_x1[T_ * D_];
__device__ float d_moe[T_ * D_];
__device__ float d_h[67108864];         // [16384, 4096]
__device__ float d_gsc[T_ * E_];
__device__ int   d_tok_e[T_ * 2];
__device__ float d_tok_w[T_ * 2];
__device__ int   d_list[T_ * 2];
__device__ float d_wl[T_ * 2];
__device__ int   d_cnt[E_];
__device__ int   d_fill[E_];
__device__ int   d_base[E_];

// ---------------- tf32 mma helpers ----------------
__device__ __forceinline__ unsigned f2tf(float f) {
    unsigned u; asm("cvt.rna.tf32.f32 %0, %1;" : "=r"(u) : "f"(f)); return u;
}
__device__ __forceinline__ void mma8(float* c, const unsigned* a, const unsigned* b) {
    asm volatile("mma.sync.aligned.m16n8k8.row.col.f32.tf32.tf32.f32 "
                 "{%0,%1,%2,%3},{%4,%5,%6,%7},{%8,%9},{%0,%1,%2,%3};"
                 : "+f"(c[0]), "+f"(c[1]), "+f"(c[2]), "+f"(c[3])
                 : "r"(a[0]), "r"(a[1]), "r"(a[2]), "r"(a[3]), "r"(b[0]), "r"(b[1]));
}

// compute one k16 slab from smem tiles; warp tile = MT*16 rows x NT2*8 cols
template <int MT, int NT2, int LDB>
__device__ __forceinline__ void compute_k16(const unsigned As[16][136], const unsigned Bs[16][LDB],
                                            int rm, int cn, int lane, float c[MT][NT2][4]) {
    const int tg = lane & 3, g = lane >> 2;
#pragma unroll
    for (int ks = 0; ks < 16; ks += 8) {
        unsigned a[MT][4], b[NT2][2];
#pragma unroll
        for (int i = 0; i < MT; i++) {
            a[i][0] = As[ks + tg][rm + i * 16 + g];
            a[i][1] = As[ks + tg][rm + i * 16 + g + 8];
            a[i][2] = As[ks + tg + 4][rm + i * 16 + g];
            a[i][3] = As[ks + tg + 4][rm + i * 16 + g + 8];
        }
#pragma unroll
        for (int j = 0; j < NT2; j++) {
            b[j][0] = Bs[ks + tg][cn + j * 8 + g];
            b[j][1] = Bs[ks + tg + 4][cn + j * 8 + g];
        }
#pragma unroll
        for (int i = 0; i < MT; i++)
#pragma unroll
            for (int j = 0; j < NT2; j++) mma8(c[i][j], a[i], b[j]);
    }
}

// ---------------- zero ----------------
__global__ void k_zero() {
    int i = blockIdx.x * 256 + threadIdx.x;
    if (i < T_ * D_) d_moe[i] = 0.f;
    if (i < E_) { d_cnt[i] = 0; d_fill[i] = 0; }
}

// ============ generic NN 128x128 tf32 gemm body ============
template <class ARowF, class EpiF>
__device__ __forceinline__ void gemm128_nn(ARowF arow_f, const float* __restrict__ B, int ldb,
                                           int col0, int nk, EpiF epi) {
    __shared__ unsigned As[16][136];
    __shared__ unsigned Bs[16][136];
    const int tid = threadIdx.x, lane = tid & 31, warp = tid >> 5;
    const int rm = (warp & 1) * 64, cn = (warp >> 1) * 32;
    float c[4][4][4];
#pragma unroll
    for (int i = 0; i < 4; i++)
#pragma unroll
        for (int j = 0; j < 4; j++)
#pragma unroll
            for (int q = 0; q < 4; q++) c[i][j][q] = 0.f;

    const int ar = tid >> 1, ak = (tid & 1) * 8;
    const int bkr = tid >> 4, bn = (tid & 15) * 8;
    const float* Ap = arow_f(ar);

    float4 ra0, ra1, rb0, rb1;
    ra0 = *(const float4*)(Ap + ak);
    ra1 = *(const float4*)(Ap + ak + 4);
    rb0 = *(const float4*)(B + (size_t)bkr * ldb + col0 + bn);
    rb1 = *(const float4*)(B + (size_t)bkr * ldb + col0 + bn + 4);

    for (int kt = 0; kt < nk; kt++) {
        As[ak + 0][ar] = f2tf(ra0.x); As[ak + 1][ar] = f2tf(ra0.y);
        As[ak + 2][ar] = f2tf(ra0.z); As[ak + 3][ar] = f2tf(ra0.w);
        As[ak + 4][ar] = f2tf(ra1.x); As[ak + 5][ar] = f2tf(ra1.y);
        As[ak + 6][ar] = f2tf(ra1.z); As[ak + 7][ar] = f2tf(ra1.w);
        Bs[bkr][bn + 0] = f2tf(rb0.x); Bs[bkr][bn + 1] = f2tf(rb0.y);
        Bs[bkr][bn + 2] = f2tf(rb0.z); Bs[bkr][bn + 3] = f2tf(rb0.w);
        Bs[bkr][bn + 4] = f2tf(rb1.x); Bs[bkr][bn + 5] = f2tf(rb1.y);
        Bs[bkr][bn + 6] = f2tf(rb1.z); Bs[bkr][bn + 7] = f2tf(rb1.w);
        __syncthreads();
        if (kt + 1 < nk) {
            int k0 = (kt + 1) * 16;
            ra0 = *(const float4*)(Ap + k0 + ak);
            ra1 = *(const float4*)(Ap + k0 + ak + 4);
            rb0 = *(const float4*)(B + (size_t)(k0 + bkr) * ldb + col0 + bn);
            rb1 = *(const float4*)(B + (size_t)(k0 + bkr) * ldb + col0 + bn + 4);
        }
        compute_k16<4, 4, 136>(As, Bs, rm, cn, lane, c);
        __syncthreads();
    }
    const int tg = lane & 3, g = lane >> 2;
#pragma unroll
    for (int i = 0; i < 4; i++) {
        int r0 = rm + i * 16 + g;
#pragma unroll
        for (int j = 0; j < 4; j++) {
            int c0 = cn + j * 8 + tg * 2;
            epi(r0, c0, c[i][j][0]); epi(r0, c0 + 1, c[i][j][1]);
            epi(r0 + 8, c0, c[i][j][2]); epi(r0 + 8, c0 + 1, c[i][j][3]);
        }
    }
}

// ---------------- QKV projection ----------------
__global__ __launch_bounds__(256) void k_qkv(
    const float* __restrict__ x,
    const float* __restrict__ Wq, const float* __restrict__ bq,
    const float* __restrict__ Wk, const float* __restrict__ bk,
    const float* __restrict__ Wv, const float* __restrict__ bv)
{
    const int which = blockIdx.z;
    const float* __restrict__ W    = which == 0 ? Wq : (which == 1 ? Wk : Wv);
    const float* __restrict__ bias = which == 0 ? bq : (which == 1 ? bk : bv);
    float* dst = which == 0 ? d_qt : (which == 1 ? d_kt : d_vt);
    const int row0 = blockIdx.y * 128, col0 = blockIdx.x * 128;
    gemm128_nn([&](int r) { return x + (size_t)(row0 + r) * D_; }, W, D_, col0, D_ / 16,
        [&](int r, int cc, float v) {
            int t = row0 + r, cg = col0 + cc;
            int bi = t >> 11, s = t & 2047, h = cg >> 6, hd = cg & 63;
            dst[(((size_t)(bi * H_ + h)) * S_ + s) * HD_ + hd] = v + bias[cg];
        });
}

// ---------------- O projection ----------------
__global__ __launch_bounds__(256) void k_oproj(const float* __restrict__ W, const float* __restrict__ bias) {
    const int row0 = blockIdx.y * 128, col0 = blockIdx.x * 128;
    gemm128_nn([&](int r) { return d_attnx + (size_t)(row0 + r) * D_; }, W, D_, col0, D_ / 16,
        [&](int r, int cc, float v) {
            d_tmp[(size_t)(row0 + r) * D_ + col0 + cc] = v + bias[col0 + cc];
        });
}

// ---------------- MoE GEMM1 (gather + gelu) ----------------
__global__ __launch_bounds__(256) void k_moe1(const float* __restrict__ eW1, const float* __restrict__ eb1) {
    const int e = blockIdx.z;
    const int cnt = d_cnt[e], base = d_base[e];
    const int row0 = blockIdx.y * 128;
    if (row0 >= cnt) return;
    const int col0 = blockIdx.x * 128;
    const float* __restrict__ W = eW1 + (size_t)e * D_ * F_;
    gemm128_nn([&](int r) {
            int rr = row0 + r;
            int token = d_list[base + (rr < cnt ? rr : 0)];
            return d_x1 + (size_t)token * D_;
        }, W, F_, col0, D_ / 16,
        [&](int r, int cc, float v) {
            int rr = row0 + r;
            if (rr < cnt) {
                float t = v + eb1[e * F_ + col0 + cc];
                d_h[(size_t)(base + rr) * F_ + col0 + cc] =
                    0.5f * t * (1.f + erff(t * 0.70710678118654752f));
            }
        });
}

// ---------------- MoE GEMM2 (weighted scatter-add) ----------------
__global__ __launch_bounds__(256) void k_moe2(const float* __restrict__ eW2, const float* __restrict__ eb2) {
    const int e = blockIdx.z;
    const int cnt = d_cnt[e], base = d_base[e];
    const int row0 = blockIdx.y * 128;
    if (row0 >= cnt) return;
    const int col0 = blockIdx.x * 128;
    const float* __restrict__ W = eW2 + (size_t)e * F_ * D_;
    gemm128_nn([&](int r) {
            int rr = row0 + r;
            return d_h + (size_t)(base + (rr < cnt ? rr : 0)) * F_;
        }, W, D_, col0, F_ / 16,
        [&](int r, int cc, float v) {
            int rr = row0 + r;
            if (rr < cnt) {
                int token = d_list[base + rr];
                float w = d_wl[base + rr];
                atomicAdd(&d_moe[(size_t)token * D_ + col0 + cc],
                          w * (v + eb2[e * D_ + col0 + cc]));
            }
        });
}

// ================= FLASH ATTENTION =================
// grid (16 qtiles, 64 bh), block 256. Warp w owns rows row0+16w .. +15.
// smem: Ks[64][136] (d-major), Vs[128][72] (seq-major). 71680 bytes dynamic.
#define LDK 136
#define LDV 72
__global__ __launch_bounds__(256) void k_flash() {
    extern __shared__ unsigned sm_[];
    unsigned* Ks = sm_;                  // [64][LDK]
    unsigned* Vs = sm_ + 64 * LDK;       // [128][LDV]
    const int bh = blockIdx.y, row0 = blockIdx.x * 128;
    const int tid = threadIdx.x, lane = tid & 31, warp = tid >> 5;
    const int tg = lane & 3, g = lane >> 2;

    const float* Kb = d_kt + (size_t)bh * S_ * HD_;
    const float* Vb = d_vt + (size_t)bh * S_ * HD_;

    // Q fragments (loop-invariant), pre-scaled by 1/sqrt(HD)=0.125
    unsigned qa[8][4];
    {
        const float* q0 = d_qt + (size_t)(bh * S_ + row0 + warp * 16 + g) * HD_;
        const float* q1 = q0 + 8 * HD_;
#pragma unroll
        for (int kd = 0; kd < 8; kd++) {
            qa[kd][0] = f2tf(0.125f * __ldg(q0 + kd * 8 + tg));
            qa[kd][1] = f2tf(0.125f * __ldg(q1 + kd * 8 + tg));
            qa[kd][2] = f2tf(0.125f * __ldg(q0 + kd * 8 + tg + 4));
            qa[kd][3] = f2tf(0.125f * __ldg(q1 + kd * 8 + tg + 4));
        }
    }

    float o[8][4];
#pragma unroll
    for (int j = 0; j < 8; j++) { o[j][0] = o[j][1] = o[j][2] = o[j][3] = 0.f; }
    float mA = -1e30f, mB = -1e30f, lA = 0.f, lB = 0.f;

    const int fc = tid >> 1;            // 0..127 (seq index within tile)
    const int fh = (tid & 1) * 32;      // headdim half

    for (int kb = 0; kb < S_ / 128; kb++) {
        // ---- fill K (transposed) and V tiles ----
        const float* kp = Kb + (size_t)(kb * 128 + fc) * HD_ + fh;
        const float* vp = Vb + (size_t)(kb * 128 + fc) * HD_ + fh;
#pragma unroll
        for (int i = 0; i < 8; i++) {
            float4 kv = *(const float4*)(kp + 4 * i);
            Ks[(fh + 4 * i + 0) * LDK + fc] = f2tf(kv.x);
            Ks[(fh + 4 * i + 1) * LDK + fc] = f2tf(kv.y);
            Ks[(fh + 4 * i + 2) * LDK + fc] = f2tf(kv.z);
            Ks[(fh + 4 * i + 3) * LDK + fc] = f2tf(kv.w);
            float4 vv = *(const float4*)(vp + 4 * i);
            Vs[fc * LDV + fh + 4 * i + 0] = f2tf(vv.x);
            Vs[fc * LDV + fh + 4 * i + 1] = f2tf(vv.y);
            Vs[fc * LDV + fh + 4 * i + 2] = f2tf(vv.z);
            Vs[fc * LDV + fh + 4 * i + 3] = f2tf(vv.w);
        }
        __syncthreads();

        // ---- S = Q @ K^T (scaled) ----
        float c[16][4];
#pragma unroll
        for (int j = 0; j < 16; j++) { c[j][0] = c[j][1] = c[j][2] = c[j][3] = 0.f; }
#pragma unroll
        for (int kd = 0; kd < 8; kd++) {
#pragma unroll
            for (int j = 0; j < 16; j++) {
                unsigned b[2] = { Ks[(kd * 8 + tg) * LDK + j * 8 + g],
                                  Ks[(kd * 8 + tg + 4) * LDK + j * 8 + g] };
                mma8(c[j], qa[kd], b);
            }
        }

        // ---- online softmax (rows g and g+8 of this warp's 16) ----
        float rmA = -1e30f, rmB = -1e30f;
#pragma unroll
        for (int j = 0; j < 16; j++) {
            rmA = fmaxf(rmA, fmaxf(c[j][0], c[j][1]));
            rmB = fmaxf(rmB, fmaxf(c[j][2], c[j][3]));
        }
        rmA = fmaxf(rmA, __shfl_xor_sync(~0u, rmA, 1));
        rmA = fmaxf(rmA, __shfl_xor_sync(~0u, rmA, 2));
        rmB = fmaxf(rmB, __shfl_xor_sync(~0u, rmB, 1));
        rmB = fmaxf(rmB, __shfl_xor_sync(~0u, rmB, 2));
        float nmA = fmaxf(mA, rmA), nmB = fmaxf(mB, rmB);
        float aA = __expf(mA - nmA), aB = __expf(mB - nmB);
        float sA = 0.f, sB = 0.f;
#pragma unroll
        for (int j = 0; j < 16; j++) {
            c[j][0] = __expf(c[j][0] - nmA); c[j][1] = __expf(c[j][1] - nmA);
            c[j][2] = __expf(c[j][2] - nmB); c[j][3] = __expf(c[j][3] - nmB);
            sA += c[j][0] + c[j][1]; sB += c[j][2] + c[j][3];
        }
        sA += __shfl_xor_sync(~0u, sA, 1); sA += __shfl_xor_sync(~0u, sA, 2);
        sB += __shfl_xor_sync(~0u, sB, 1); sB += __shfl_xor_sync(~0u, sB, 2);
        lA = lA * aA + sA; lB = lB * aB + sB;
        mA = nmA; mB = nmB;
#pragma unroll
        for (int j = 0; j < 8; j++) {
            o[j][0] *= aA; o[j][1] *= aA; o[j][2] *= aB; o[j][3] *= aB;
        }

        // ---- O += P @ V  (P fragment via shuffles from C-frag) ----
        const int srcA = (lane & 28) | (tg >> 1);
        const bool hi = tg & 1;
#pragma unroll
        for (int t = 0; t < 16; t++) {
            float v00 = __shfl_sync(~0u, c[t][0], srcA);
            float v01 = __shfl_sync(~0u, c[t][1], srcA);
            float v02 = __shfl_sync(~0u, c[t][2], srcA);
            float v03 = __shfl_sync(~0u, c[t][3], srcA);
            float v10 = __shfl_sync(~0u, c[t][0], srcA + 2);
            float v11 = __shfl_sync(~0u, c[t][1], srcA + 2);
            float v12 = __shfl_sync(~0u, c[t][2], srcA + 2);
            float v13 = __shfl_sync(~0u, c[t][3], srcA + 2);
            unsigned a[4] = { f2tf(hi ? v01 : v00), f2tf(hi ? v03 : v02),
                              f2tf(hi ? v11 : v10), f2tf(hi ? v13 : v12) };
#pragma unroll
            for (int jo = 0; jo < 8; jo++) {
                unsigned b[2] = { Vs[(t * 8 + tg) * LDV + jo * 8 + g],
                                  Vs[(t * 8 + tg + 4) * LDV + jo * 8 + g] };
                mma8(o[jo], a, b);
            }
        }
        __syncthreads();
    }

    // ---- epilogue: divide by l, write to d_attnx[t, h*64+col] ----
    const float iA = 1.f / lA, iB = 1.f / lB;
    const int b_ = bh >> 4, h = bh & 15;
    const int rA = row0 + warp * 16 + g;
    float* oA = d_attnx + ((size_t)(b_ * S_ + rA)) * D_ + h * HD_;
    float* oB = oA + 8 * D_;
#pragma unroll
    for (int jo = 0; jo < 8; jo++) {
        *(float2*)(oA + jo * 8 + tg * 2) = make_float2(o[jo][0] * iA, o[jo][1] * iA);
        *(float2*)(oB + jo * 8 + tg * 2) = make_float2(o[jo][2] * iB, o[jo][3] * iB);
    }
}

// ---------------- layernorm ----------------
__device__ __forceinline__ void ln_body(const float* __restrict__ a, const float* __restrict__ add,
                                        const float* __restrict__ g, const float* __restrict__ be,
                                        float* __restrict__ out) {
    const int t = blockIdx.x, tid = threadIdx.x;
    __shared__ float v[D_];
    __shared__ float red[256];
    float s = 0.f;
    for (int j = tid; j < D_; j += 256) {
        float xv = a[(size_t)t * D_ + j] + add[(size_t)t * D_ + j];
        v[j] = xv; s += xv;
    }
    red[tid] = s; __syncthreads();
    for (int o = 128; o > 0; o >>= 1) { if (tid < o) red[tid] += red[tid + o]; __syncthreads(); }
    float mu = red[0] * (1.f / D_); __syncthreads();
    float s2 = 0.f;
    for (int j = tid; j < D_; j += 256) { float d = v[j] - mu; s2 += d * d; }
    red[tid] = s2; __syncthreads();
    for (int o = 128; o > 0; o >>= 1) { if (tid < o) red[tid] += red[tid + o]; __syncthreads(); }
    float rstd = rsqrtf(red[0] * (1.f / D_) + 1e-5f);
    for (int j = tid; j < D_; j += 256)
        out[(size_t)t * D_ + j] = (v[j] - mu) * rstd * g[j] + be[j];
}
__global__ __launch_bounds__(256) void k_ln1(const float* __restrict__ x,
                                             const float* __restrict__ g, const float* __restrict__ be) {
    ln_body(x, d_tmp, g, be, d_x1);
}
__global__ __launch_bounds__(256) void k_ln2(const float* __restrict__ g, const float* __restrict__ be,
                                             float* __restrict__ out) {
    ln_body(d_x1, d_moe, g, be, out);
}

// ---------------- routing ----------------
__global__ __launch_bounds__(128) void k_route(const float* __restrict__ gW, const float* __restrict__ gb) {
    const int t = blockIdx.x, tid = threadIdx.x;
    float p[E_];
#pragma unroll
    for (int e = 0; e < E_; e++) p[e] = 0.f;
    for (int d = tid; d < D_; d += 128) {
        float xv = d_x1[(size_t)t * D_ + d];
        const float* w = gW + (size_t)d * E_;
#pragma unroll
        for (int e = 0; e < E_; e++) p[e] += xv * w[e];
    }
    __shared__ float red[128][E_];
#pragma unroll
    for (int e = 0; e < E_; e++) red[tid][e] = p[e];
    __syncthreads();
    for (int o = 64; o > 0; o >>= 1) {
        if (tid < o) {
#pragma unroll
            for (int e = 0; e < E_; e++) red[tid][e] += red[tid + o][e];
        }
        __syncthreads();
    }
    if (tid == 0) {
        float l[E_], m = -1e30f;
#pragma unroll
        for (int e = 0; e < E_; e++) { l[e] = red[0][e] + gb[e]; m = fmaxf(m, l[e]); }
        float s = 0.f;
#pragma unroll
        for (int e = 0; e < E_; e++) { l[e] = expf(l[e] - m); s += l[e]; }
        float inv = 1.f / s;
#pragma unroll
        for (int e = 0; e < E_; e++) { l[e] *= inv; d_gsc[t * E_ + e] = l[e]; }
        int i1 = 0;
#pragma unroll
        for (int e = 1; e < E_; e++) if (l[e] > l[i1]) i1 = e;
        int i2 = -1;
#pragma unroll
        for (int e = 0; e < E_; e++) if (e != i1 && (i2 < 0 || l[e] > l[i2])) i2 = e;
        float tot = l[i1] + l[i2];
        d_tok_e[t * 2 + 0] = i1; d_tok_e[t * 2 + 1] = i2;
        d_tok_w[t * 2 + 0] = l[i1] / tot; d_tok_w[t * 2 + 1] = l[i2] / tot;
        atomicAdd(&d_cnt[i1], 1); atomicAdd(&d_cnt[i2], 1);
    }
}

__global__ __launch_bounds__(256) void k_aux(float* __restrict__ aux_out) {
    __shared__ double red[256];
    __shared__ double rw[E_];
    const int tid = threadIdx.x;
    for (int e = 0; e < E_; e++) {
        double s = 0.0;
        for (int t = tid; t < T_; t += 256) s += (double)d_gsc[t * E_ + e];
        red[tid] = s; __syncthreads();
        for (int o = 128; o > 0; o >>= 1) { if (tid < o) red[tid] += red[tid + o]; __syncthreads(); }
        if (tid == 0) rw[e] = red[0] / (double)T_;
        __syncthreads();
    }
    if (tid == 0) {
        double aux = 0.0; int b = 0;
        for (int e = 0; e < E_; e++) {
            aux += ((double)d_cnt[e] / (double)(T_ * 2)) * rw[e];
            d_base[e] = b; b += d_cnt[e];
        }
        *aux_out = (float)((double)E_ * aux);
    }
}

__global__ void k_fill() {
    const int t = blockIdx.x * 256 + threadIdx.x;
    if (t >= T_) return;
    for (int k = 0; k < 2; k++) {
        int e = d_tok_e[t * 2 + k];
        int slot = atomicAdd(&d_fill[e], 1);
        d_list[d_base[e] + slot] = t;
        d_wl[d_base[e] + slot] = d_tok_w[t * 2 + k];
    }
}

// ---------------- launch ----------------
extern "C" void kernel_launch(void* const* d_in, const int* in_sizes, int n_in,
                              void* d_out, int out_size) {
    const float* x     = (const float*)d_in[0];
    const float* Wq    = (const float*)d_in[1];
    const float* bq    = (const float*)d_in[2];
    const float* Wk    = (const float*)d_in[3];
    const float* bk    = (const float*)d_in[4];
    const float* Wv    = (const float*)d_in[5];
    const float* bv    = (const float*)d_in[6];
    const float* Wo    = (const float*)d_in[7];
    const float* bo    = (const float*)d_in[8];
    const float* g1    = (const float*)d_in[9];
    const float* beta1 = (const float*)d_in[10];
    const float* gateW = (const float*)d_in[11];
    const float* gateb = (const float*)d_in[12];
    const float* eW1   = (const float*)d_in[13];
    const float* eb1   = (const float*)d_in[14];
    const float* eW2   = (const float*)d_in[15];
    const float* eb2   = (const float*)d_in[16];
    const float* g2    = (const float*)d_in[17];
    const float* beta2 = (const float*)d_in[18];
    float* out = (float*)d_out;

    const int flash_smem = (64 * LDK + 128 * LDV) * 4;  // 71680 B
    static int attr_set = 0;
    if (!attr_set) {
        cudaFuncSetAttribute(k_flash, cudaFuncAttributeMaxDynamicSharedMemorySize, flash_smem);
        attr_set = 1;
    }

    k_zero<<<(T_ * D_) / 256, 256>>>();
    k_qkv<<<dim3(D_ / 128, T_ / 128, 3), 256>>>(x, Wq, bq, Wk, bk, Wv, bv);
    k_flash<<<dim3(S_ / 128, BH_), 256, flash_smem>>>();
    k_oproj<<<dim3(D_ / 128, T_ / 128), 256>>>(Wo, bo);
    k_ln1<<<T_, 256>>>(x, g1, beta1);
    k_route<<<T_, 128>>>(gateW, gateb);
    k_aux<<<1, 256>>>(out + (out_size - 1));
    k_fill<<<T_ / 256, 256>>>();
    k_moe1<<<dim3(F_ / 128, T_ / 128, E_), 256>>>(eW1, eb1);
    k_moe2<<<dim3(D_ / 128, T_ / 128, E_), 256>>>(eW2, eb2);
    k_ln2<<<T_, 256>>>(g2, beta2, out);
}